// round 2
// baseline (speedup 1.0000x reference)
#include <cuda_runtime.h>

// Problem constants
namespace {
constexpr int B  = 4;
constexpr int S  = 1024;
constexpr int DM = 512;
constexpr int DA = 512;
constexpr int H  = 8;
constexpr int F  = 16;
}

// Scratch (static device globals -- no allocations allowed)
__device__ float g_qp [B * S * DA];      // 8 MB
__device__ float g_kp [B * S * DA];      // 8 MB
__device__ float g_vp [B * S * DA];      // 8 MB
__device__ float g_x  [B * S * H * F];   // 2 MB
__device__ float g_ctx[B * S * DA];      // 8 MB

// ---------------------------------------------------------------------------
// Generic SGEMM with bias: C[M,N] = A[M,K] @ W[K,N] + bias[N]
// Tile 64x64, K-chunk 16, 256 threads, 4x4 micro-tile. M%64==0, N%64==0, K%16==0.
// ---------------------------------------------------------------------------
__global__ __launch_bounds__(256) void sgemm_bias_kernel(
    const float* __restrict__ A, const float* __restrict__ W,
    const float* __restrict__ bias, float* __restrict__ C,
    int M, int N, int K)
{
    __shared__ float As[16][64];   // [k][m]
    __shared__ float Bs[16][64];   // [k][n]
    const int tid = threadIdx.x;
    const int m0 = blockIdx.y * 64;
    const int n0 = blockIdx.x * 64;
    const int tm = (tid & 15) * 4;
    const int tn = (tid >> 4) * 4;
    const int ar  = tid >> 2;          // 0..63 (m row)
    const int ak  = (tid & 3) * 4;     // 0,4,8,12 (k)
    const int bkr = tid >> 4;          // 0..15 (k row)
    const int bnc = (tid & 15) * 4;    // n col
    float acc[4][4] = {};
    for (int k0 = 0; k0 < K; k0 += 16) {
        const float4 a = *(const float4*)&A[(size_t)(m0 + ar) * K + k0 + ak];
        As[ak + 0][ar] = a.x; As[ak + 1][ar] = a.y;
        As[ak + 2][ar] = a.z; As[ak + 3][ar] = a.w;
        *(float4*)&Bs[bkr][bnc] = *(const float4*)&W[(size_t)(k0 + bkr) * N + n0 + bnc];
        __syncthreads();
#pragma unroll
        for (int kk = 0; kk < 16; kk++) {
            const float4 av = *(const float4*)&As[kk][tm];
            const float4 bv = *(const float4*)&Bs[kk][tn];
            const float aa[4] = {av.x, av.y, av.z, av.w};
            const float bb[4] = {bv.x, bv.y, bv.z, bv.w};
#pragma unroll
            for (int i = 0; i < 4; i++)
#pragma unroll
                for (int j = 0; j < 4; j++)
                    acc[i][j] = fmaf(aa[i], bb[j], acc[i][j]);
        }
        __syncthreads();
    }
    const float4 bb4 = *(const float4*)&bias[n0 + tn];
#pragma unroll
    for (int i = 0; i < 4; i++) {
        float4 o;
        o.x = acc[i][0] + bb4.x;
        o.y = acc[i][1] + bb4.y;
        o.z = acc[i][2] + bb4.z;
        o.w = acc[i][3] + bb4.w;
        *(float4*)&C[(size_t)(m0 + tm + i) * N + n0 + tn] = o;
    }
}

// ---------------------------------------------------------------------------
// xdiff bias: logits[b,h,q,k] = 0.5 * sum_f xdiff[b,q,k,f] * x[b,q,h*F+f]
// One CTA per (b,q); reads xdiff exactly once. Writes the whole logits buffer.
// ---------------------------------------------------------------------------
__global__ __launch_bounds__(256) void xbias_kernel(
    const float* __restrict__ xdiff, const float* __restrict__ xg,
    float* __restrict__ logits)
{
    __shared__ float xh[H * F];    // 128 floats
    const int bq  = blockIdx.x;            // b*S + q
    const int b   = bq >> 10;
    const int qi  = bq & 1023;
    const int tid = threadIdx.x;
    if (tid < H * F) xh[tid] = xg[(size_t)bq * (H * F) + tid];
    __syncthreads();
    const float* xd = xdiff + (size_t)bq * S * F;
#pragma unroll
    for (int kt = 0; kt < 4; kt++) {
        const int k = kt * 256 + tid;
        const float4* src = (const float4*)&xd[(size_t)k * F];
        const float4 t0 = src[0], t1 = src[1], t2 = src[2], t3 = src[3];
        const float xv[16] = {t0.x, t0.y, t0.z, t0.w, t1.x, t1.y, t1.z, t1.w,
                              t2.x, t2.y, t2.z, t2.w, t3.x, t3.y, t3.z, t3.w};
#pragma unroll
        for (int h = 0; h < H; h++) {
            float s = 0.0f;
#pragma unroll
            for (int f = 0; f < F; f++) s = fmaf(xv[f], xh[h * F + f], s);
            logits[((size_t)(b * H + h) * S + qi) * S + k] = 0.5f * s;
        }
    }
}

// ---------------------------------------------------------------------------
// QK^T accumulate: logits[b,h,q,k] += (1/8) * sum_d qp[b,q,h*64+d]*kp[b,k,h*64+d]
// Per-(b,h) batched GEMM [S,64]x[64,S], 64x64 tile, K=64 in one shot.
// ---------------------------------------------------------------------------
__global__ __launch_bounds__(256) void qk_kernel(
    const float* __restrict__ qp, const float* __restrict__ kp,
    float* __restrict__ logits)
{
    __shared__ float Qs[64][64];   // [d][q]
    __shared__ float Ks[64][64];   // [d][k]
    const int tid = threadIdx.x;
    const int bh  = blockIdx.z;
    const int b   = bh >> 3;
    const int h   = bh & 7;
    const int q0  = blockIdx.y * 64;
    const int k0  = blockIdx.x * 64;
    const float* Qb = qp + (size_t)b * S * DA + h * 64;
    const float* Kb = kp + (size_t)b * S * DA + h * 64;
#pragma unroll
    for (int p = 0; p < 4; p++) {
        const int r = p * 16 + (tid >> 4);
        const int c = (tid & 15) * 4;
        const float4 a = *(const float4*)&Qb[(size_t)(q0 + r) * DA + c];
        Qs[c + 0][r] = a.x; Qs[c + 1][r] = a.y;
        Qs[c + 2][r] = a.z; Qs[c + 3][r] = a.w;
        const float4 kv = *(const float4*)&Kb[(size_t)(k0 + r) * DA + c];
        Ks[c + 0][r] = kv.x; Ks[c + 1][r] = kv.y;
        Ks[c + 2][r] = kv.z; Ks[c + 3][r] = kv.w;
    }
    __syncthreads();
    const int tm = (tid & 15) * 4;
    const int tn = (tid >> 4) * 4;
    float acc[4][4] = {};
#pragma unroll
    for (int kk = 0; kk < 64; kk++) {
        const float4 av = *(const float4*)&Qs[kk][tm];
        const float4 bv = *(const float4*)&Ks[kk][tn];
        const float aa[4] = {av.x, av.y, av.z, av.w};
        const float bb[4] = {bv.x, bv.y, bv.z, bv.w};
#pragma unroll
        for (int i = 0; i < 4; i++)
#pragma unroll
            for (int j = 0; j < 4; j++)
                acc[i][j] = fmaf(aa[i], bb[j], acc[i][j]);
    }
    float* Cb = logits + (size_t)bh * S * S;
    constexpr float sc = 0.125f;   // 1/sqrt(64)
#pragma unroll
    for (int i = 0; i < 4; i++) {
        float4* pC = (float4*)&Cb[(size_t)(q0 + tm + i) * S + k0 + tn];
        float4 c = *pC;
        c.x = fmaf(acc[i][0], sc, c.x);
        c.y = fmaf(acc[i][1], sc, c.y);
        c.z = fmaf(acc[i][2], sc, c.z);
        c.w = fmaf(acc[i][3], sc, c.w);
        *pC = c;
    }
}

// ---------------------------------------------------------------------------
// In-place softmax over the last dim (S=1024). One CTA (256 thr) per row.
// ---------------------------------------------------------------------------
__global__ __launch_bounds__(256) void softmax_kernel(float* __restrict__ attn)
{
    __shared__ float red[256];
    const int tid = threadIdx.x;
    float* p = attn + (size_t)blockIdx.x * S;
    float4 v = *(float4*)&p[tid * 4];
    float m = fmaxf(fmaxf(v.x, v.y), fmaxf(v.z, v.w));
    red[tid] = m;
    __syncthreads();
    for (int s = 128; s > 0; s >>= 1) {
        if (tid < s) red[tid] = fmaxf(red[tid], red[tid + s]);
        __syncthreads();
    }
    m = red[0];
    __syncthreads();
    float4 e;
    e.x = __expf(v.x - m); e.y = __expf(v.y - m);
    e.z = __expf(v.z - m); e.w = __expf(v.w - m);
    red[tid] = e.x + e.y + e.z + e.w;
    __syncthreads();
    for (int s = 128; s > 0; s >>= 1) {
        if (tid < s) red[tid] += red[tid + s];
        __syncthreads();
    }
    const float inv = 1.0f / red[0];
    e.x *= inv; e.y *= inv; e.z *= inv; e.w *= inv;
    *(float4*)&p[tid * 4] = e;
}

// ---------------------------------------------------------------------------
// PV: ctx[b,q,h*64+d] = sum_k attn[b,h,q,k] * vp[b,k,h*64+d]
// Per-(b,h) GEMM [S,S]x[S,64]; 64(q)x64(d) tile, K-chunk 32.
// ---------------------------------------------------------------------------
__global__ __launch_bounds__(256) void pv_kernel(
    const float* __restrict__ attn, const float* __restrict__ vp,
    float* __restrict__ ctx)
{
    __shared__ float Ps[32][64];   // [k][q]
    __shared__ float Vs[32][64];   // [k][d]
    const int tid = threadIdx.x;
    const int bh  = blockIdx.y;
    const int b   = bh >> 3;
    const int h   = bh & 7;
    const int q0  = blockIdx.x * 64;
    const float* Ab = attn + ((size_t)bh * S + q0) * S;
    const float* Vb = vp + (size_t)b * S * DA + h * 64;
    const int tm = (tid & 15) * 4;
    const int tn = (tid >> 4) * 4;
    float acc[4][4] = {};
    for (int k0 = 0; k0 < S; k0 += 32) {
#pragma unroll
        for (int p = 0; p < 2; p++) {
            const int r = p * 32 + (tid >> 3);
            const int c = (tid & 7) * 4;
            const float4 a = *(const float4*)&Ab[(size_t)r * S + k0 + c];
            Ps[c + 0][r] = a.x; Ps[c + 1][r] = a.y;
            Ps[c + 2][r] = a.z; Ps[c + 3][r] = a.w;
        }
#pragma unroll
        for (int p = 0; p < 2; p++) {
            const int kr = p * 16 + (tid >> 4);
            const int c  = (tid & 15) * 4;
            *(float4*)&Vs[kr][c] = *(const float4*)&Vb[(size_t)(k0 + kr) * DA + c];
        }
        __syncthreads();
#pragma unroll
        for (int kk = 0; kk < 32; kk++) {
            const float4 av = *(const float4*)&Ps[kk][tm];
            const float4 bv = *(const float4*)&Vs[kk][tn];
            const float aa[4] = {av.x, av.y, av.z, av.w};
            const float bb[4] = {bv.x, bv.y, bv.z, bv.w};
#pragma unroll
            for (int i = 0; i < 4; i++)
#pragma unroll
                for (int j = 0; j < 4; j++)
                    acc[i][j] = fmaf(aa[i], bb[j], acc[i][j]);
        }
        __syncthreads();
    }
#pragma unroll
    for (int i = 0; i < 4; i++) {
        const float4 o = make_float4(acc[i][0], acc[i][1], acc[i][2], acc[i][3]);
        *(float4*)&ctx[(size_t)(b * S + q0 + tm + i) * DA + h * 64 + tn] = o;
    }
}

// ---------------------------------------------------------------------------
extern "C" void kernel_launch(void* const* d_in, const int* in_sizes, int n_in,
                              void* d_out, int out_size)
{
    const float* q     = (const float*)d_in[0];
    const float* k     = (const float*)d_in[1];
    const float* v     = (const float*)d_in[2];
    const float* xdiff = (const float*)d_in[3];
    const float* Wq    = (const float*)d_in[4];
    const float* bq    = (const float*)d_in[5];
    const float* Wk    = (const float*)d_in[6];
    const float* bk    = (const float*)d_in[7];
    const float* Wv    = (const float*)d_in[8];
    const float* bv    = (const float*)d_in[9];
    const float* Wx    = (const float*)d_in[10];
    const float* bx    = (const float*)d_in[11];
    const float* Wo    = (const float*)d_in[12];
    const float* bo    = (const float*)d_in[13];

    float* out_final = (float*)d_out;                       // [B,S,DM]
    float* attn      = out_final + (size_t)B * S * DM;      // [B,H,S,S]

    float *qp, *kp, *vp, *xg, *ctx;
    cudaGetSymbolAddress((void**)&qp,  g_qp);
    cudaGetSymbolAddress((void**)&kp,  g_kp);
    cudaGetSymbolAddress((void**)&vp,  g_vp);
    cudaGetSymbolAddress((void**)&xg,  g_x);
    cudaGetSymbolAddress((void**)&ctx, g_ctx);

    const dim3 blk(256);

    // 1-3. q/k/v projections: [4096,512] @ [512,512] + bias
    const dim3 gP(DA / 64, (B * S) / 64);
    sgemm_bias_kernel<<<gP, blk>>>(q, Wq, bq, qp, B * S, DA, DM);
    sgemm_bias_kernel<<<gP, blk>>>(k, Wk, bk, kp, B * S, DA, DM);
    sgemm_bias_kernel<<<gP, blk>>>(v, Wv, bv, vp, B * S, DA, DM);

    // 4. x = qp @ Wx + bx : [4096,512] @ [512,128]
    const dim3 gX((H * F) / 64, (B * S) / 64);
    sgemm_bias_kernel<<<gX, blk>>>(qp, Wx, bx, xg, B * S, H * F, DA);

    // 5. xdiff relative bias -> writes entire logits buffer (attn region)
    xbias_kernel<<<B * S, blk>>>(xdiff, xg, attn);

    // 6. += QK^T / sqrt(D)
    const dim3 gQK(S / 64, S / 64, B * H);
    qk_kernel<<<gQK, blk>>>(qp, kp, attn);

    // 7. softmax in place -> final attn output
    softmax_kernel<<<B * H * S, blk>>>(attn);

    // 8. ctx = attn @ V (per b,h), laid out as [B,S,DA]
    const dim3 gPV(S / 64, B * H);
    pv_kernel<<<gPV, blk>>>(attn, vp, ctx);

    // 9. output = ctx @ Wo + bo
    const dim3 gO(DM / 64, (B * S) / 64);
    sgemm_bias_kernel<<<gO, blk>>>(ctx, Wo, bo, out_final, B * S, DM, DA);
}

// round 3
// speedup vs baseline: 1.4305x; 1.4305x over previous
#include <cuda_runtime.h>

// Problem constants
namespace {
constexpr int B  = 4;
constexpr int S  = 1024;
constexpr int DM = 512;
constexpr int DA = 512;
constexpr int H  = 8;
constexpr int F  = 16;
}

// Scratch (static device globals -- no allocations allowed)
__device__ float g_qp [B * S * DA];      // 8 MB
__device__ float g_kp [B * S * DA];      // 8 MB
__device__ float g_vp [B * S * DA];      // 8 MB
__device__ float g_x  [B * S * H * F];   // 2 MB
__device__ float g_ctx[B * S * DA];      // 8 MB

// ---------------------------------------------------------------------------
// tf32 helpers
// ---------------------------------------------------------------------------
__device__ __forceinline__ unsigned f2tf(float f) {
    unsigned u;
    asm("cvt.rna.tf32.f32 %0, %1;" : "=r"(u) : "f"(f));
    return u;
}

__device__ __forceinline__ void mma_tf32(float c[4],
                                         unsigned a0, unsigned a1, unsigned a2, unsigned a3,
                                         unsigned b0, unsigned b1) {
    asm volatile(
        "mma.sync.aligned.m16n8k8.row.col.f32.tf32.tf32.f32 "
        "{%0,%1,%2,%3}, {%4,%5,%6,%7}, {%8,%9}, {%0,%1,%2,%3};"
        : "+f"(c[0]), "+f"(c[1]), "+f"(c[2]), "+f"(c[3])
        : "r"(a0), "r"(a1), "r"(a2), "r"(a3), "r"(b0), "r"(b1));
}

// ---------------------------------------------------------------------------
// Generic tf32 GEMM with bias: C[M,N] = A[M,K] @ W[K,N] + bias[N]
// BM=128, BN=128, BK=16, 256 threads (8 warps, 64x32 warp tile).
// M%128==0, N%128==0, K%16==0.
// ---------------------------------------------------------------------------
__global__ __launch_bounds__(256) void gemm_bias_tf32(
    const float* __restrict__ A, const float* __restrict__ W,
    const float* __restrict__ bias, float* __restrict__ C,
    int M, int N, int K)
{
    constexpr int ASTR = 20;    // 16 + 4 pad  (As[m][k])
    constexpr int BSTR = 132;   // 128 + 4 pad (Bs[k][n])
    __shared__ unsigned As[128 * ASTR];
    __shared__ unsigned Bs[16 * BSTR];

    const int tid  = threadIdx.x;
    const int warp = tid >> 5;
    const int lane = tid & 31;
    const int gid  = lane >> 2;
    const int tig  = lane & 3;
    const int wm   = (warp & 1) * 64;
    const int wn   = (warp >> 1) * 32;
    const int m0   = blockIdx.y * 128;
    const int n0   = blockIdx.x * 128;

    // A-load indices: 2 float4/thread
    const int am  = tid >> 2;            // row 0..63 (and +64)
    const int ak4 = (tid & 3) * 4;
    // B-load indices: 2 float4/thread
    const int bk  = tid >> 5;            // k row 0..7 (and +8)
    const int bn4 = (tid & 31) * 4;

    float4 ra0, ra1, rb0, rb1;
    {
        const float* Ap = A + (size_t)(m0 + am) * K + ak4;
        ra0 = *(const float4*)Ap;
        ra1 = *(const float4*)(Ap + (size_t)64 * K);
        const float* Wp = W + (size_t)bk * N + n0 + bn4;
        rb0 = *(const float4*)Wp;
        rb1 = *(const float4*)(Wp + (size_t)8 * N);
    }

    float acc[4][4][4] = {};

    for (int k0 = 0; k0 < K; k0 += 16) {
        // stage into smem (with tf32 conversion)
        {
            unsigned* p0 = &As[am * ASTR + ak4];
            p0[0] = f2tf(ra0.x); p0[1] = f2tf(ra0.y); p0[2] = f2tf(ra0.z); p0[3] = f2tf(ra0.w);
            unsigned* p1 = &As[(am + 64) * ASTR + ak4];
            p1[0] = f2tf(ra1.x); p1[1] = f2tf(ra1.y); p1[2] = f2tf(ra1.z); p1[3] = f2tf(ra1.w);
            unsigned* q0 = &Bs[bk * BSTR + bn4];
            q0[0] = f2tf(rb0.x); q0[1] = f2tf(rb0.y); q0[2] = f2tf(rb0.z); q0[3] = f2tf(rb0.w);
            unsigned* q1 = &Bs[(bk + 8) * BSTR + bn4];
            q1[0] = f2tf(rb1.x); q1[1] = f2tf(rb1.y); q1[2] = f2tf(rb1.z); q1[3] = f2tf(rb1.w);
        }
        __syncthreads();
        if (k0 + 16 < K) {
            const float* Ap = A + (size_t)(m0 + am) * K + k0 + 16 + ak4;
            ra0 = *(const float4*)Ap;
            ra1 = *(const float4*)(Ap + (size_t)64 * K);
            const float* Wp = W + (size_t)(k0 + 16 + bk) * N + n0 + bn4;
            rb0 = *(const float4*)Wp;
            rb1 = *(const float4*)(Wp + (size_t)8 * N);
        }
#pragma unroll
        for (int ks = 0; ks < 2; ks++) {
            unsigned afr[4][4];
#pragma unroll
            for (int mi = 0; mi < 4; mi++) {
                const int mr = wm + mi * 16 + gid;
                afr[mi][0] = As[mr * ASTR + ks * 8 + tig];
                afr[mi][1] = As[(mr + 8) * ASTR + ks * 8 + tig];
                afr[mi][2] = As[mr * ASTR + ks * 8 + tig + 4];
                afr[mi][3] = As[(mr + 8) * ASTR + ks * 8 + tig + 4];
            }
            unsigned bfr[4][2];
#pragma unroll
            for (int ni = 0; ni < 4; ni++) {
                const int nc = wn + ni * 8 + gid;
                bfr[ni][0] = Bs[(ks * 8 + tig) * BSTR + nc];
                bfr[ni][1] = Bs[(ks * 8 + tig + 4) * BSTR + nc];
            }
#pragma unroll
            for (int mi = 0; mi < 4; mi++)
#pragma unroll
                for (int ni = 0; ni < 4; ni++)
                    mma_tf32(acc[mi][ni], afr[mi][0], afr[mi][1], afr[mi][2], afr[mi][3],
                             bfr[ni][0], bfr[ni][1]);
        }
        __syncthreads();
    }

    // epilogue: bias + store
#pragma unroll
    for (int mi = 0; mi < 4; mi++) {
        const int row = m0 + wm + mi * 16 + gid;
#pragma unroll
        for (int ni = 0; ni < 4; ni++) {
            const int col = n0 + wn + ni * 8 + 2 * tig;
            const float2 bb = *(const float2*)&bias[col];
            float2 o0, o1;
            o0.x = acc[mi][ni][0] + bb.x; o0.y = acc[mi][ni][1] + bb.y;
            o1.x = acc[mi][ni][2] + bb.x; o1.y = acc[mi][ni][3] + bb.y;
            *(float2*)&C[(size_t)row * N + col]       = o0;
            *(float2*)&C[(size_t)(row + 8) * N + col] = o1;
        }
    }
}

// ---------------------------------------------------------------------------
// QK^T accumulate (tf32): logits[b,h,q,k] += (1/8)*sum_d qp[..]*kp[..]
// Per-(b,h) GEMM [S,64]x[64,S]; BM=BN=128, full K=64 in 2 chunks of 32.
// Both smem tiles stored row-major [row][d] with stride 36 -> conflict-free frags.
// ---------------------------------------------------------------------------
__global__ __launch_bounds__(256) void qk_tf32(
    const float* __restrict__ qp, const float* __restrict__ kp,
    float* __restrict__ logits)
{
    constexpr int STR = 36;     // 32 + 4 pad
    __shared__ unsigned Qs[128 * STR];
    __shared__ unsigned Ks[128 * STR];

    const int tid  = threadIdx.x;
    const int warp = tid >> 5;
    const int lane = tid & 31;
    const int gid  = lane >> 2;
    const int tig  = lane & 3;
    const int wm   = (warp & 1) * 64;
    const int wn   = (warp >> 1) * 32;

    const int bh = blockIdx.z;
    const int b  = bh >> 3;
    const int h  = bh & 7;
    const int q0 = blockIdx.y * 128;
    const int k0 = blockIdx.x * 128;

    const float* Qb = qp + (size_t)b * S * DA + h * 64;
    const float* Kb = kp + (size_t)b * S * DA + h * 64;

    // loads: 4 float4 per thread per tile
    const int lm  = tid >> 3;            // row 0..31 (+32p)
    const int lk4 = (tid & 7) * 4;

    float acc[4][4][4] = {};

    for (int kc = 0; kc < 64; kc += 32) {
#pragma unroll
        for (int p = 0; p < 4; p++) {
            const int r = lm + 32 * p;
            const float4 qv = *(const float4*)&Qb[(size_t)(q0 + r) * DA + kc + lk4];
            unsigned* pq = &Qs[r * STR + lk4];
            pq[0] = f2tf(qv.x); pq[1] = f2tf(qv.y); pq[2] = f2tf(qv.z); pq[3] = f2tf(qv.w);
            const float4 kv = *(const float4*)&Kb[(size_t)(k0 + r) * DA + kc + lk4];
            unsigned* pk = &Ks[r * STR + lk4];
            pk[0] = f2tf(kv.x); pk[1] = f2tf(kv.y); pk[2] = f2tf(kv.z); pk[3] = f2tf(kv.w);
        }
        __syncthreads();
#pragma unroll
        for (int ks = 0; ks < 4; ks++) {
            unsigned afr[4][4];
#pragma unroll
            for (int mi = 0; mi < 4; mi++) {
                const int mr = wm + mi * 16 + gid;
                afr[mi][0] = Qs[mr * STR + ks * 8 + tig];
                afr[mi][1] = Qs[(mr + 8) * STR + ks * 8 + tig];
                afr[mi][2] = Qs[mr * STR + ks * 8 + tig + 4];
                afr[mi][3] = Qs[(mr + 8) * STR + ks * 8 + tig + 4];
            }
            unsigned bfr[4][2];
#pragma unroll
            for (int ni = 0; ni < 4; ni++) {
                const int nc = wn + ni * 8 + gid;
                bfr[ni][0] = Ks[nc * STR + ks * 8 + tig];
                bfr[ni][1] = Ks[nc * STR + ks * 8 + tig + 4];
            }
#pragma unroll
            for (int mi = 0; mi < 4; mi++)
#pragma unroll
                for (int ni = 0; ni < 4; ni++)
                    mma_tf32(acc[mi][ni], afr[mi][0], afr[mi][1], afr[mi][2], afr[mi][3],
                             bfr[ni][0], bfr[ni][1]);
        }
        __syncthreads();
    }

    float* Cb = logits + (size_t)bh * S * S;
    constexpr float sc = 0.125f;   // 1/sqrt(64)
#pragma unroll
    for (int mi = 0; mi < 4; mi++) {
        const int row = q0 + wm + mi * 16 + gid;
#pragma unroll
        for (int ni = 0; ni < 4; ni++) {
            const int col = k0 + wn + ni * 8 + 2 * tig;
            float2 p0 = *(float2*)&Cb[(size_t)row * S + col];
            float2 p1 = *(float2*)&Cb[(size_t)(row + 8) * S + col];
            p0.x = fmaf(acc[mi][ni][0], sc, p0.x);
            p0.y = fmaf(acc[mi][ni][1], sc, p0.y);
            p1.x = fmaf(acc[mi][ni][2], sc, p1.x);
            p1.y = fmaf(acc[mi][ni][3], sc, p1.y);
            *(float2*)&Cb[(size_t)row * S + col]       = p0;
            *(float2*)&Cb[(size_t)(row + 8) * S + col] = p1;
        }
    }
}

// ---------------------------------------------------------------------------
// PV (tf32): ctx[b,q,h*64+d] = sum_k attn[b,h,q,k] * vp[b,k,h*64+d]
// Per-(b,h) GEMM [S,S]x[S,64]; BM=128 (q), BN=64 (d), BK=32; prefetched.
// ---------------------------------------------------------------------------
__global__ __launch_bounds__(256) void pv_tf32(
    const float* __restrict__ attn, const float* __restrict__ vp,
    float* __restrict__ ctx)
{
    constexpr int ASTR = 36;    // Ps[q][k], 32+4
    constexpr int BSTR = 68;    // Vs[k][d], 64+4
    __shared__ unsigned Ps[128 * ASTR];
    __shared__ unsigned Vs[32 * BSTR];

    const int tid  = threadIdx.x;
    const int warp = tid >> 5;
    const int lane = tid & 31;
    const int gid  = lane >> 2;
    const int tig  = lane & 3;
    const int wm   = (warp >> 1) * 32;   // 4 warps in M
    const int wn   = (warp & 1) * 32;    // 2 warps in N

    const int bh = blockIdx.y;
    const int b  = bh >> 3;
    const int h  = bh & 7;
    const int q0 = blockIdx.x * 128;

    const float* Ab = attn + ((size_t)bh * S + q0) * S;
    const float* Vb = vp + (size_t)b * S * DA + h * 64;

    // A loads: 4 float4/thread; V loads: 2 float4/thread
    const int lm  = tid >> 3;            // 0..31 (+32p)
    const int lk4 = (tid & 7) * 4;
    const int vk  = tid >> 4;            // 0..15 (+16)
    const int vn4 = (tid & 15) * 4;

    float4 rp[4], rv[2];
#pragma unroll
    for (int p = 0; p < 4; p++)
        rp[p] = *(const float4*)&Ab[(size_t)(lm + 32 * p) * S + lk4];
    rv[0] = *(const float4*)&Vb[(size_t)vk * DA + vn4];
    rv[1] = *(const float4*)&Vb[(size_t)(vk + 16) * DA + vn4];

    float acc[2][4][4] = {};

    for (int k0 = 0; k0 < S; k0 += 32) {
#pragma unroll
        for (int p = 0; p < 4; p++) {
            unsigned* pp = &Ps[(lm + 32 * p) * ASTR + lk4];
            pp[0] = f2tf(rp[p].x); pp[1] = f2tf(rp[p].y);
            pp[2] = f2tf(rp[p].z); pp[3] = f2tf(rp[p].w);
        }
        {
            unsigned* pv0 = &Vs[vk * BSTR + vn4];
            pv0[0] = f2tf(rv[0].x); pv0[1] = f2tf(rv[0].y);
            pv0[2] = f2tf(rv[0].z); pv0[3] = f2tf(rv[0].w);
            unsigned* pv1 = &Vs[(vk + 16) * BSTR + vn4];
            pv1[0] = f2tf(rv[1].x); pv1[1] = f2tf(rv[1].y);
            pv1[2] = f2tf(rv[1].z); pv1[3] = f2tf(rv[1].w);
        }
        __syncthreads();
        if (k0 + 32 < S) {
#pragma unroll
            for (int p = 0; p < 4; p++)
                rp[p] = *(const float4*)&Ab[(size_t)(lm + 32 * p) * S + k0 + 32 + lk4];
            rv[0] = *(const float4*)&Vb[(size_t)(k0 + 32 + vk) * DA + vn4];
            rv[1] = *(const float4*)&Vb[(size_t)(k0 + 48 + vk) * DA + vn4];
        }
#pragma unroll
        for (int ks = 0; ks < 4; ks++) {
            unsigned afr[2][4];
#pragma unroll
            for (int mi = 0; mi < 2; mi++) {
                const int mr = wm + mi * 16 + gid;
                afr[mi][0] = Ps[mr * ASTR + ks * 8 + tig];
                afr[mi][1] = Ps[(mr + 8) * ASTR + ks * 8 + tig];
                afr[mi][2] = Ps[mr * ASTR + ks * 8 + tig + 4];
                afr[mi][3] = Ps[(mr + 8) * ASTR + ks * 8 + tig + 4];
            }
            unsigned bfr[4][2];
#pragma unroll
            for (int ni = 0; ni < 4; ni++) {
                const int nc = wn + ni * 8 + gid;
                bfr[ni][0] = Vs[(ks * 8 + tig) * BSTR + nc];
                bfr[ni][1] = Vs[(ks * 8 + tig + 4) * BSTR + nc];
            }
#pragma unroll
            for (int mi = 0; mi < 2; mi++)
#pragma unroll
                for (int ni = 0; ni < 4; ni++)
                    mma_tf32(acc[mi][ni], afr[mi][0], afr[mi][1], afr[mi][2], afr[mi][3],
                             bfr[ni][0], bfr[ni][1]);
        }
        __syncthreads();
    }

#pragma unroll
    for (int mi = 0; mi < 2; mi++) {
        const int row = q0 + wm + mi * 16 + gid;
#pragma unroll
        for (int ni = 0; ni < 4; ni++) {
            const int col = wn + ni * 8 + 2 * tig;
            float2 o0, o1;
            o0.x = acc[mi][ni][0]; o0.y = acc[mi][ni][1];
            o1.x = acc[mi][ni][2]; o1.y = acc[mi][ni][3];
            *(float2*)&ctx[(size_t)(b * S + row) * DA + h * 64 + col]     = o0;
            *(float2*)&ctx[(size_t)(b * S + row + 8) * DA + h * 64 + col] = o1;
        }
    }
}

// ---------------------------------------------------------------------------
// xdiff bias: logits[b,h,q,k] = 0.5 * sum_f xdiff[b,q,k,f] * x[b,q,h*F+f]
// ---------------------------------------------------------------------------
__global__ __launch_bounds__(256) void xbias_kernel(
    const float* __restrict__ xdiff, const float* __restrict__ xg,
    float* __restrict__ logits)
{
    __shared__ float xh[H * F];
    const int bq  = blockIdx.x;
    const int b   = bq >> 10;
    const int qi  = bq & 1023;
    const int tid = threadIdx.x;
    if (tid < H * F) xh[tid] = xg[(size_t)bq * (H * F) + tid];
    __syncthreads();
    const float* xd = xdiff + (size_t)bq * S * F;
#pragma unroll
    for (int kt = 0; kt < 4; kt++) {
        const int k = kt * 256 + tid;
        const float4* src = (const float4*)&xd[(size_t)k * F];
        const float4 t0 = src[0], t1 = src[1], t2 = src[2], t3 = src[3];
        const float xv[16] = {t0.x, t0.y, t0.z, t0.w, t1.x, t1.y, t1.z, t1.w,
                              t2.x, t2.y, t2.z, t2.w, t3.x, t3.y, t3.z, t3.w};
#pragma unroll
        for (int h = 0; h < H; h++) {
            float s = 0.0f;
#pragma unroll
            for (int f = 0; f < F; f++) s = fmaf(xv[f], xh[h * F + f], s);
            logits[((size_t)(b * H + h) * S + qi) * S + k] = 0.5f * s;
        }
    }
}

// ---------------------------------------------------------------------------
// In-place softmax over the last dim (S=1024). One CTA (256 thr) per row.
// ---------------------------------------------------------------------------
__global__ __launch_bounds__(256) void softmax_kernel(float* __restrict__ attn)
{
    __shared__ float red[256];
    const int tid = threadIdx.x;
    float* p = attn + (size_t)blockIdx.x * S;
    float4 v = *(float4*)&p[tid * 4];
    float m = fmaxf(fmaxf(v.x, v.y), fmaxf(v.z, v.w));
    red[tid] = m;
    __syncthreads();
    for (int s = 128; s > 0; s >>= 1) {
        if (tid < s) red[tid] = fmaxf(red[tid], red[tid + s]);
        __syncthreads();
    }
    m = red[0];
    __syncthreads();
    float4 e;
    e.x = __expf(v.x - m); e.y = __expf(v.y - m);
    e.z = __expf(v.z - m); e.w = __expf(v.w - m);
    red[tid] = e.x + e.y + e.z + e.w;
    __syncthreads();
    for (int s = 128; s > 0; s >>= 1) {
        if (tid < s) red[tid] += red[tid + s];
        __syncthreads();
    }
    const float inv = 1.0f / red[0];
    e.x *= inv; e.y *= inv; e.z *= inv; e.w *= inv;
    *(float4*)&p[tid * 4] = e;
}

// ---------------------------------------------------------------------------
extern "C" void kernel_launch(void* const* d_in, const int* in_sizes, int n_in,
                              void* d_out, int out_size)
{
    const float* q     = (const float*)d_in[0];
    const float* k     = (const float*)d_in[1];
    const float* v     = (const float*)d_in[2];
    const float* xdiff = (const float*)d_in[3];
    const float* Wq    = (const float*)d_in[4];
    const float* bq    = (const float*)d_in[5];
    const float* Wk    = (const float*)d_in[6];
    const float* bk    = (const float*)d_in[7];
    const float* Wv    = (const float*)d_in[8];
    const float* bv    = (const float*)d_in[9];
    const float* Wx    = (const float*)d_in[10];
    const float* bx    = (const float*)d_in[11];
    const float* Wo    = (const float*)d_in[12];
    const float* bo    = (const float*)d_in[13];

    float* out_final = (float*)d_out;                       // [B,S,DM]
    float* attn      = out_final + (size_t)B * S * DM;      // [B,H,S,S]

    float *qp, *kp, *vp, *xg, *ctx;
    cudaGetSymbolAddress((void**)&qp,  g_qp);
    cudaGetSymbolAddress((void**)&kp,  g_kp);
    cudaGetSymbolAddress((void**)&vp,  g_vp);
    cudaGetSymbolAddress((void**)&xg,  g_x);
    cudaGetSymbolAddress((void**)&ctx, g_ctx);

    const dim3 blk(256);

    // 1-3. q/k/v projections: [4096,512] @ [512,512] + bias  (tensor cores)
    const dim3 gP(DA / 128, (B * S) / 128);
    gemm_bias_tf32<<<gP, blk>>>(q, Wq, bq, qp, B * S, DA, DM);
    gemm_bias_tf32<<<gP, blk>>>(k, Wk, bk, kp, B * S, DA, DM);
    gemm_bias_tf32<<<gP, blk>>>(v, Wv, bv, vp, B * S, DA, DM);

    // 4. x = qp @ Wx + bx : [4096,512] @ [512,128]
    const dim3 gX((H * F) / 128, (B * S) / 128);
    gemm_bias_tf32<<<gX, blk>>>(qp, Wx, bx, xg, B * S, H * F, DA);

    // 5. xdiff relative bias -> writes entire logits buffer (attn region)
    xbias_kernel<<<B * S, blk>>>(xdiff, xg, attn);

    // 6. += QK^T / sqrt(D)   (tensor cores)
    const dim3 gQK(S / 128, S / 128, B * H);
    qk_tf32<<<gQK, blk>>>(qp, kp, attn);

    // 7. softmax in place -> final attn output
    softmax_kernel<<<B * H * S, blk>>>(attn);

    // 8. ctx = attn @ V (per b,h), laid out as [B,S,DA]   (tensor cores)
    const dim3 gPV(S / 128, B * H);
    pv_tf32<<<gPV, blk>>>(attn, vp, ctx);

    // 9. output = ctx @ Wo + bo   (tensor cores)
    const dim3 gO(DM / 128, (B * S) / 128);
    gemm_bias_tf32<<<gO, blk>>>(ctx, Wo, bo, out_final, B * S, DM, DA);
}